// round 5
// baseline (speedup 1.0000x reference)
#include <cuda_runtime.h>
#include <cstdint>

#define EPS     1e-8f
#define PSD_EPS 1e-5f

constexpr int B = 8, C = 8, F = 257, T = 1500;
constexpr int BF  = B * F;                       // 2056
constexpr long long FT  = (long long)F * T;      // 385500
constexpr long long BFT = (long long)B * F * T;  // 3084000
constexpr int T4 = T / 4;                        // 375

typedef unsigned long long u64;

// Scratch (no allocations allowed)
__device__ float g_pmax[2][B][4][T];   // partial max over F-chunks
__device__ float g_recip[2][B][T];     // 1/(max_f |mask| + eps)
__device__ float g_acc[BF][2][66];     // per (b,f), per mask: [0..7] diag, [8+2p],[9+2p] offdiag re/im, [64] den
__device__ float g_w[BF][C][2];        // conj(weight) per (b,f,c)

// ---- packed f32x2 helpers (Blackwell: fma.rn.f32x2 only via PTX) ----------
__device__ __forceinline__ u64 pk(float lo, float hi) {
    u64 r; asm("mov.b64 %0,{%1,%2};" : "=l"(r) : "f"(lo), "f"(hi)); return r;
}
__device__ __forceinline__ void unpk(u64 v, float& lo, float& hi) {
    asm("mov.b64 {%0,%1},%2;" : "=f"(lo), "=f"(hi) : "l"(v));
}
__device__ __forceinline__ void fma2(u64& d, u64 a, u64 b) {
    asm("fma.rn.f32x2 %0,%1,%2,%0;" : "+l"(d) : "l"(a), "l"(b));
}
__device__ __forceinline__ u64 mul2(u64 a, u64 b) {
    u64 r; asm("mul.rn.f32x2 %0,%1,%2;" : "=l"(r) : "l"(a), "l"(b)); return r;
}

// ---------------------------------------------------------------------------
// Kernel 1a: partial max over F-chunk of |mask|, float4 along t.
// grid = 2*B*4 blocks, 384 threads (375 active).
// ---------------------------------------------------------------------------
__global__ void mask_max_part(const float* __restrict__ sm,
                              const float* __restrict__ nm) {
    int blk = blockIdx.x;
    int chunk = blk & 3, b = (blk >> 2) & 7, m = blk >> 5;
    int i = threadIdx.x;
    if (i >= T4) return;
    int fs = chunk ? 65 + (chunk - 1) * 64 : 0;
    int fe = fs + (chunk ? 64 : 65);
    const float4* src = (const float4*)((m ? nm : sm) + (long long)b * FT);
    float4 mx = make_float4(0.f, 0.f, 0.f, 0.f);
    for (int f = fs; f < fe; f++) {
        float4 v = src[(long long)f * T4 + i];
        mx.x = fmaxf(mx.x, fabsf(v.x));
        mx.y = fmaxf(mx.y, fabsf(v.y));
        mx.z = fmaxf(mx.z, fabsf(v.z));
        mx.w = fmaxf(mx.w, fabsf(v.w));
    }
    ((float4*)g_pmax[m][b][chunk])[i] = mx;
}

// Kernel 1b: combine 4 partials -> reciprocal. grid = 16, 384 threads.
__global__ void mask_recip_kernel() {
    int blk = blockIdx.x;
    int b = blk & 7, m = blk >> 3;
    int i = threadIdx.x;
    if (i >= T4) return;
    float4 a = ((float4*)g_pmax[m][b][0])[i];
    #pragma unroll
    for (int c = 1; c < 4; c++) {
        float4 v = ((float4*)g_pmax[m][b][c])[i];
        a.x = fmaxf(a.x, v.x); a.y = fmaxf(a.y, v.y);
        a.z = fmaxf(a.z, v.z); a.w = fmaxf(a.w, v.w);
    }
    float4 r;
    r.x = 1.0f / (a.x + EPS); r.y = 1.0f / (a.y + EPS);
    r.z = 1.0f / (a.z + EPS); r.w = 1.0f / (a.w + EPS);
    ((float4*)g_recip[m][b])[i] = r;
}

// ---------------------------------------------------------------------------
// Kernel 2: per-(b,f) mask-weighted Hermitian outer-product accumulation,
// packed f32x2 math. One block per (b,f), 128 threads stride over t.
// Deterministic binary smem-tree reduction.
// ---------------------------------------------------------------------------
__global__ __launch_bounds__(128, 2) void psd_accum_kernel(
    const float* __restrict__ sm, const float* __restrict__ nm,
    const float* __restrict__ cr, const float* __restrict__ ci) {
    int bf = blockIdx.x;
    int b = bf / F, f = bf % F;
    const float* crb = cr + (long long)b * C * FT + (long long)f * T;
    const float* cib = ci + (long long)b * C * FT + (long long)f * T;
    const float* smb = sm + (long long)b * FT + (long long)f * T;
    const float* nmb = nm + (long long)b * FT + (long long)f * T;
    const float* rs = g_recip[0][b];
    const float* rn = g_recip[1][b];

    u64 offS[28], offN[28], dg[8];
    float denS = 0.f, denN = 0.f;
    #pragma unroll
    for (int p = 0; p < 28; p++) { offS[p] = 0ull; offN[p] = 0ull; }
    #pragma unroll
    for (int c = 0; c < 8; c++) dg[c] = 0ull;

    for (int t = threadIdx.x; t < T; t += 128) {
        float ms = smb[t] * rs[t];
        float mn = nmb[t] * rn[t];
        u64 msmn = pk(ms, mn), ms2 = pk(ms, ms), mn2 = pk(mn, mn);
        denS += ms; denN += mn;

        float xr[8], xi[8];
        #pragma unroll
        for (int c = 0; c < 8; c++) {
            xr[c] = crb[(long long)c * FT + t];
            xi[c] = cib[(long long)c * FT + t];
        }
        u64 a[8], aw[8];
        #pragma unroll
        for (int c = 0; c < 8; c++) {
            a[c]  = pk(xr[c], xi[c]);
            aw[c] = pk(xi[c], xr[c]);
        }
        #pragma unroll
        for (int c = 0; c < 8; c++) {
            float p = fmaf(xr[c], xr[c], xi[c] * xi[c]);
            fma2(dg[c], msmn, pk(p, p));        // (s,n) diag accumulate
        }
        #pragma unroll
        for (int d = 1; d < 8; d++) {
            u64 bx = pk(xr[d], xr[d]);
            u64 by = pk(xi[d], -xi[d]);
            #pragma unroll
            for (int c = 0; c < d; c++) {
                int p = c * 7 - (c * (c - 1)) / 2 + (d - c - 1);
                // o = (xr_c*xr_d + xi_c*xi_d,  xi_c*xr_d - xr_c*xi_d)
                u64 o = mul2(a[c], bx);
                fma2(o, aw[c], by);
                fma2(offS[p], ms2, o);
                fma2(offN[p], mn2, o);
            }
        }
    }

    // Unpack into canonical layout
    float r[130];
    #pragma unroll
    for (int c = 0; c < 8; c++) unpk(dg[c], r[c], r[65 + c]);
    #pragma unroll
    for (int p = 0; p < 28; p++) {
        unpk(offS[p], r[8 + 2 * p], r[9 + 2 * p]);
        unpk(offN[p], r[73 + 2 * p], r[74 + 2 * p]);
    }
    r[64] = denS; r[129] = denN;

    // deterministic binary tree over shared memory (stride 133: conflict-free)
    __shared__ float sh[64][133];
    int tid = threadIdx.x;
    #pragma unroll 1
    for (int off = 64; off >= 1; off >>= 1) {
        if (tid >= off && tid < 2 * off) {
            for (int k = 0; k < 130; k++) sh[tid - off][k] = r[k];
        }
        __syncthreads();
        if (tid < off) {
            for (int k = 0; k < 130; k++) r[k] += sh[tid][k];
        }
        __syncthreads();
    }
    if (tid == 0) {
        for (int k = 0; k < 65; k++) g_acc[bf][0][k] = r[k];
        for (int k = 0; k < 65; k++) g_acc[bf][1][k] = r[65 + k];
    }
}

// ---------------------------------------------------------------------------
// Kernel 3: per-(b,f) solve (unchanged from round 2).
// ---------------------------------------------------------------------------
__device__ __forceinline__ int pidx(int c, int d) {
    return c * 7 - (c * (c - 1)) / 2 + (d - c - 1);
}

__device__ __forceinline__ void getS(const float* a, float invs,
                                     int r, int c, float& re, float& im) {
    const float IM0 = PSD_EPS + EPS;
    if (r == c)      { re = a[r] * invs;                 im = IM0; }
    else if (r < c)  { int p = pidx(r, c);
                       re = a[8 + 2 * p] * invs;         im = a[9 + 2 * p] * invs + IM0; }
    else             { int p = pidx(c, r);
                       re = a[8 + 2 * p] * invs;         im = -a[9 + 2 * p] * invs + IM0; }
}

__global__ void solve_kernel() {
    int bf = blockIdx.x * blockDim.x + threadIdx.x;
    if (bf >= BF) return;
    const float IM0 = PSD_EPS + EPS;

    const float* an = g_acc[bf][1];
    float invd = 1.0f / fmaxf(an[64], PSD_EPS);
    float Nr[8][8], Ni[8][8];
    #pragma unroll
    for (int c = 0; c < 8; c++) {
        Nr[c][c] = an[c] * invd + EPS;
        Ni[c][c] = IM0;
        #pragma unroll
        for (int d = c + 1; d < 8; d++) {
            int p = pidx(c, d);
            float re = an[8 + 2 * p] * invd, im = an[9 + 2 * p] * invd;
            Nr[c][d] = re; Ni[c][d] = im + IM0;
            Nr[d][c] = re; Ni[d][c] = -im + IM0;
        }
    }

    #pragma unroll
    for (int k = 0; k < 8; k++) {
        float pr = Nr[k][k], pi = Ni[k][k];
        float s = 1.0f / (pr * pr + pi * pi);
        float qr = pr * s, qi = -pi * s;
        #pragma unroll
        for (int j = 0; j < 8; j++) if (j != k) {
            float ar = Nr[k][j], ai = Ni[k][j];
            Nr[k][j] = ar * qr - ai * qi;
            Ni[k][j] = ar * qi + ai * qr;
        }
        Nr[k][k] = qr; Ni[k][k] = qi;
        #pragma unroll
        for (int i = 0; i < 8; i++) if (i != k) {
            float fr = Nr[i][k], fi = Ni[i][k];
            #pragma unroll
            for (int j = 0; j < 8; j++) if (j != k) {
                float br = Nr[k][j], bi = Ni[k][j];
                Nr[i][j] -= fr * br - fi * bi;
                Ni[i][j] -= fr * bi + fi * br;
            }
            Nr[i][k] = -(fr * qr - fi * qi);
            Ni[i][k] = -(fr * qi + fi * qr);
        }
    }

    #pragma unroll
    for (int c = 0; c < 8; c++)
        #pragma unroll
        for (int d = 0; d < 8; d++) Ni[c][d] += EPS;

    const float* as_ = g_acc[bf][0];
    float invs = 1.0f / fmaxf(as_[64], PSD_EPS);

    float trr = EPS, tri = 0.0f;
    #pragma unroll
    for (int c = 0; c < 8; c++) {
        #pragma unroll
        for (int d = 0; d < 8; d++) {
            float sr, si; getS(as_, invs, d, c, sr, si);
            float ar = Nr[c][d], ai = Ni[c][d];
            trr += ar * sr - ai * si;
            tri += ar * si + ai * sr;
        }
    }
    float ur[8], ui[8];
    #pragma unroll
    for (int c = 0; c < 8; c++) {
        float sumr = 0.0f, sumi = 0.0f;
        #pragma unroll
        for (int d = 0; d < 8; d++) {
            float sr, si; getS(as_, invs, d, 0, sr, si);
            float ar = Nr[c][d], ai = Ni[c][d];
            sumr += ar * sr - ai * si;
            sumi += ar * si + ai * sr;
        }
        ur[c] = sumr; ui[c] = sumi;
    }
    float tm = 1.0f / (trr * trr + tri * tri);
    #pragma unroll
    for (int c = 0; c < 8; c++) {
        float wr = (ur[c] * trr + ui[c] * tri) * tm;
        float wi = (ui[c] * trr - ur[c] * tri) * tm;
        g_w[bf][c][0] = wr;
        g_w[bf][c][1] = -wi;
    }
}

// ---------------------------------------------------------------------------
// Kernel 4: beamform, float4-vectorized. One block per (b,f), 128 threads.
// ---------------------------------------------------------------------------
__global__ __launch_bounds__(128) void beamform_kernel(
    const float* __restrict__ cr, const float* __restrict__ ci,
    float* __restrict__ out) {
    int bf = blockIdx.x;
    int b = bf / F, f = bf % F;
    float wr[8], wi[8];
    #pragma unroll
    for (int c = 0; c < 8; c++) {
        wr[c] = g_w[bf][c][0];
        wi[c] = g_w[bf][c][1];
    }
    const float4* cr4 = (const float4*)(cr + (long long)b * C * FT + (long long)f * T);
    const float4* ci4 = (const float4*)(ci + (long long)b * C * FT + (long long)f * T);
    float4* outr = (float4*)(out + (long long)bf * T);
    float4* outi = (float4*)(out + BFT + (long long)bf * T);
    constexpr int FT4 = (int)(FT / 4);   // 96375

    for (int i = threadIdx.x; i < T4; i += 128) {
        float4 orv = make_float4(0.f, 0.f, 0.f, 0.f);
        float4 oiv = make_float4(0.f, 0.f, 0.f, 0.f);
        #pragma unroll
        for (int c = 0; c < 8; c++) {
            float4 xr = cr4[c * FT4 + i];
            float4 xi = ci4[c * FT4 + i];
            orv.x = fmaf(wr[c], xr.x, fmaf(-wi[c], xi.x, orv.x));
            orv.y = fmaf(wr[c], xr.y, fmaf(-wi[c], xi.y, orv.y));
            orv.z = fmaf(wr[c], xr.z, fmaf(-wi[c], xi.z, orv.z));
            orv.w = fmaf(wr[c], xr.w, fmaf(-wi[c], xi.w, orv.w));
            oiv.x = fmaf(wr[c], xi.x, fmaf(wi[c], xr.x, oiv.x));
            oiv.y = fmaf(wr[c], xi.y, fmaf(wi[c], xr.y, oiv.y));
            oiv.z = fmaf(wr[c], xi.z, fmaf(wi[c], xr.z, oiv.z));
            oiv.w = fmaf(wr[c], xi.w, fmaf(wi[c], xr.w, oiv.w));
        }
        outr[i] = orv;
        outi[i] = oiv;
    }
}

// ---------------------------------------------------------------------------
extern "C" void kernel_launch(void* const* d_in, const int* in_sizes, int n_in,
                              void* d_out, int out_size) {
    const float* sm = (const float*)d_in[0];
    const float* nm = (const float*)d_in[1];
    const float* cr = (const float*)d_in[2];
    const float* ci = (const float*)d_in[3];
    float* out = (float*)d_out;

    mask_max_part<<<64, 384>>>(sm, nm);
    mask_recip_kernel<<<16, 384>>>();
    psd_accum_kernel<<<BF, 128>>>(sm, nm, cr, ci);
    solve_kernel<<<(BF + 127) / 128, 128>>>();
    beamform_kernel<<<BF, 128>>>(cr, ci, out);
}

// round 8
// speedup vs baseline: 1.7437x; 1.7437x over previous
#include <cuda_runtime.h>

#define EPS     1e-8f
#define PSD_EPS 1e-5f

constexpr int B = 8, C = 8, F = 257, T = 1500;
constexpr int BF  = B * F;                       // 2056
constexpr long long FT  = (long long)F * T;      // 385500
constexpr long long BFT = (long long)B * F * T;  // 3084000
constexpr int T2 = T / 2;                        // 750
constexpr int T4 = T / 4;                        // 375
constexpr int FT2 = (int)(FT / 2);               // 192750
constexpr int FT4 = (int)(FT / 4);               // 96375

// Scratch (no allocations allowed)
__device__ float g_pmax[2][B][4][T];
__device__ float g_recip[2][B][T];

// ---------------------------------------------------------------------------
// Kernel 1a: partial max over F-chunk of |mask|, float4 along t.
// ---------------------------------------------------------------------------
__global__ void mask_max_part(const float* __restrict__ sm,
                              const float* __restrict__ nm) {
    int blk = blockIdx.x;
    int chunk = blk & 3, b = (blk >> 2) & 7, m = blk >> 5;
    int i = threadIdx.x;
    if (i >= T4) return;
    int fs = chunk ? 65 + (chunk - 1) * 64 : 0;
    int fe = fs + (chunk ? 64 : 65);
    const float4* src = (const float4*)((m ? nm : sm) + (long long)b * FT);
    float4 mx = make_float4(0.f, 0.f, 0.f, 0.f);
    for (int f = fs; f < fe; f++) {
        float4 v = src[(long long)f * T4 + i];
        mx.x = fmaxf(mx.x, fabsf(v.x));
        mx.y = fmaxf(mx.y, fabsf(v.y));
        mx.z = fmaxf(mx.z, fabsf(v.z));
        mx.w = fmaxf(mx.w, fabsf(v.w));
    }
    ((float4*)g_pmax[m][b][chunk])[i] = mx;
}

// Kernel 1b: combine 4 partials -> reciprocal.
__global__ void mask_recip_kernel() {
    int blk = blockIdx.x;
    int b = blk & 7, m = blk >> 3;
    int i = threadIdx.x;
    if (i >= T4) return;
    float4 a = ((float4*)g_pmax[m][b][0])[i];
    #pragma unroll
    for (int c = 1; c < 4; c++) {
        float4 v = ((float4*)g_pmax[m][b][c])[i];
        a.x = fmaxf(a.x, v.x); a.y = fmaxf(a.y, v.y);
        a.z = fmaxf(a.z, v.z); a.w = fmaxf(a.w, v.w);
    }
    float4 r;
    r.x = 1.0f / (a.x + EPS); r.y = 1.0f / (a.y + EPS);
    r.z = 1.0f / (a.z + EPS); r.w = 1.0f / (a.w + EPS);
    ((float4*)g_recip[m][b])[i] = r;
}

// ---------------------------------------------------------------------------
// Fused kernel: PSD accumulate -> reduce -> 64-thread-parallel solve ->
// beamform, one block per (b,f). Beamform re-reads cm from (hot) L2.
// ---------------------------------------------------------------------------
__device__ __forceinline__ int pidx(int c, int d) {
    return c * 7 - (c * (c - 1)) / 2 + (d - c - 1);
}

// S[r][c] of the speech PSD from the canonical accumulator layout
__device__ __forceinline__ void getS(const float* a, float invs,
                                     int r, int c, float& re, float& im) {
    const float IM0 = PSD_EPS + EPS;
    if (r == c)      { re = a[r] * invs;                 im = IM0; }
    else if (r < c)  { int p = pidx(r, c);
                       re = a[8 + 2 * p] * invs;         im = a[9 + 2 * p] * invs + IM0; }
    else             { int p = pidx(c, r);
                       re = a[8 + 2 * p] * invs;         im = -a[9 + 2 * p] * invs + IM0; }
}

__device__ __forceinline__ void accum_point(float* acc, const float* xr,
                                            const float* xi, float ms, float mn) {
    acc[64]  += ms;
    acc[129] += mn;
    #pragma unroll
    for (int c = 0; c < 8; c++) {
        float p = fmaf(xr[c], xr[c], xi[c] * xi[c]);
        acc[c]      = fmaf(ms, p, acc[c]);
        acc[65 + c] = fmaf(mn, p, acc[65 + c]);
    }
    #pragma unroll
    for (int c = 0; c < 8; c++) {
        #pragma unroll
        for (int d = c + 1; d < 8; d++) {
            int p = pidx(c, d);
            float orr = fmaf(xr[c], xr[d], xi[c] * xi[d]);
            float oii = fmaf(xi[c], xr[d], -xr[c] * xi[d]);
            acc[8 + 2 * p]  = fmaf(ms, orr, acc[8 + 2 * p]);
            acc[9 + 2 * p]  = fmaf(ms, oii, acc[9 + 2 * p]);
            acc[73 + 2 * p] = fmaf(mn, orr, acc[73 + 2 * p]);
            acc[74 + 2 * p] = fmaf(mn, oii, acc[74 + 2 * p]);
        }
    }
}

__global__ __launch_bounds__(128) void mvdr_fused_kernel(
    const float* __restrict__ sm, const float* __restrict__ nm,
    const float* __restrict__ cr, const float* __restrict__ ci,
    float* __restrict__ out) {
    int bf = blockIdx.x;
    int b = bf / F, f = bf % F;
    int tid = threadIdx.x;
    int lane = tid & 31, wid = tid >> 5;

    const float* crb = cr + (long long)b * C * FT + (long long)f * T;
    const float* cib = ci + (long long)b * C * FT + (long long)f * T;
    const float2* cr2 = (const float2*)crb;
    const float2* ci2 = (const float2*)cib;
    const float2* smb = (const float2*)(sm + (long long)b * FT + (long long)f * T);
    const float2* nmb = (const float2*)(nm + (long long)b * FT + (long long)f * T);
    const float2* rs = (const float2*)(g_recip[0][b]);
    const float2* rn = (const float2*)(g_recip[1][b]);

    // ---- Phase A: PSD accumulation (float2 along t) ----
    float acc[130];
    #pragma unroll
    for (int k = 0; k < 130; k++) acc[k] = 0.f;

    for (int i = tid; i < T2; i += 128) {
        float2 a = smb[i], ra = rs[i], bm = nmb[i], rb = rn[i];
        float xr0[8], xi0[8], xr1[8], xi1[8];
        #pragma unroll
        for (int c = 0; c < 8; c++) {
            float2 vr = cr2[c * FT2 + i];
            float2 vi = ci2[c * FT2 + i];
            xr0[c] = vr.x; xr1[c] = vr.y;
            xi0[c] = vi.x; xi1[c] = vi.y;
        }
        accum_point(acc, xr0, xi0, a.x * ra.x, bm.x * rb.x);
        accum_point(acc, xr1, xi1, a.y * ra.y, bm.y * rb.y);
    }

    // ---- Phase B: deterministic reduction (warp shfl + cross-warp smem) ----
    __shared__ float sh[4][132];
    __shared__ float sacc[130];
    #pragma unroll
    for (int k = 0; k < 130; k++) {
        float v = acc[k];
        v += __shfl_down_sync(0xffffffffu, v, 16);
        v += __shfl_down_sync(0xffffffffu, v, 8);
        v += __shfl_down_sync(0xffffffffu, v, 4);
        v += __shfl_down_sync(0xffffffffu, v, 2);
        v += __shfl_down_sync(0xffffffffu, v, 1);
        if (lane == 0) sh[wid][k] = v;
    }
    __syncthreads();
    for (int k = tid; k < 130; k += 128)
        sacc[k] = sh[0][k] + sh[1][k] + sh[2][k] + sh[3][k];
    __syncthreads();

    // ---- Phase C: entry-parallel solve (threads 0..63, one complex entry each)
    __shared__ float rowr[8], rowi[8], colr[8], coli[8];
    __shared__ float sur[8], sui[8], strv[2];
    __shared__ float swr[8], swi[8];
    const float* aS = &sacc[0];
    const float* aN = &sacc[65];
    const float IM0 = PSD_EPS + EPS;
    int i8 = tid >> 3, j8 = tid & 7;
    float nr = 0.f, ni = 0.f;

    if (tid < 64) {
        float invd = 1.0f / fmaxf(aN[64], PSD_EPS);
        if (i8 == j8)      { nr = aN[i8] * invd + EPS;  ni = IM0; }
        else if (i8 < j8)  { int p = pidx(i8, j8);
                             nr = aN[8 + 2 * p] * invd; ni = aN[9 + 2 * p] * invd + IM0; }
        else               { int p = pidx(j8, i8);
                             nr = aN[8 + 2 * p] * invd; ni = -aN[9 + 2 * p] * invd + IM0; }
    }

    // Gauss-Jordan, no pivoting (matrix is strongly diagonally dominant)
    #pragma unroll
    for (int k = 0; k < 8; k++) {
        if (tid < 64) {
            if (i8 == k) { rowr[j8] = nr; rowi[j8] = ni; }   // raw row k
            if (j8 == k) { colr[i8] = nr; coli[i8] = ni; }   // raw col k
        }
        __syncthreads();
        if (tid < 64) {
            float pr = rowr[k], pi = rowi[k];
            float s = 1.0f / fmaf(pr, pr, pi * pi);
            float qr = pr * s, qi = -pi * s;
            if (i8 == k) {
                if (j8 == k) { nr = qr; ni = qi; }
                else { float ar = nr, ai = ni;
                       nr = ar * qr - ai * qi; ni = ar * qi + ai * qr; }
            } else {
                float fr = colr[i8], fi = coli[i8];
                float gr = fr * qr - fi * qi, gi = fr * qi + fi * qr;  // f/p
                if (j8 == k) { nr = -gr; ni = -gi; }
                else {
                    float br = rowr[j8], bi = rowi[j8];                // raw a_kj
                    nr -= gr * br - gi * bi;
                    ni -= gr * bi + gi * br;
                }
            }
        }
        __syncthreads();
    }

    // tr = eps + sum ninv[c][d]*S[d][c];  u[c] = sum_d ninv[c][d]*S[d][0]
    if (tid < 64) {
        ni += EPS;                       // ninv + 1j*eps
        float invs = 1.0f / fmaxf(aS[64], PSD_EPS);
        float sr, si;
        getS(aS, invs, j8, i8, sr, si);
        float tre = nr * sr - ni * si, tim = nr * si + ni * sr;
        getS(aS, invs, j8, 0, sr, si);
        float ue = nr * sr - ni * si, uim = nr * si + ni * sr;
        #pragma unroll
        for (int o = 1; o < 8; o <<= 1) {
            ue  += __shfl_xor_sync(0xffffffffu, ue, o);
            uim += __shfl_xor_sync(0xffffffffu, uim, o);
        }
        if (j8 == 0) { sur[i8] = ue; sui[i8] = uim; }
        #pragma unroll
        for (int o = 16; o >= 1; o >>= 1) {
            tre += __shfl_down_sync(0xffffffffu, tre, o);
            tim += __shfl_down_sync(0xffffffffu, tim, o);
        }
        if (lane == 0) { sh[wid][0] = tre; sh[wid][1] = tim; }
    }
    __syncthreads();
    if (tid == 0) {
        strv[0] = EPS + sh[0][0] + sh[1][0];
        strv[1] = sh[0][1] + sh[1][1];
    }
    __syncthreads();
    if (tid < 8) {
        float trr = strv[0], tri = strv[1];
        float tm = 1.0f / fmaf(trr, trr, tri * tri);
        float ur = sur[tid], ui = sui[tid];
        float wr = (ur * trr + ui * tri) * tm;    // Re(u/tr)
        float wi = (ui * trr - ur * tri) * tm;    // Im(u/tr)
        swr[tid] = wr;
        swi[tid] = -wi;                           // conj(weight)
    }
    __syncthreads();

    // ---- Phase D: beamform (cm slice is L2-hot), float4 along t ----
    float wr[8], wi[8];
    #pragma unroll
    for (int c = 0; c < 8; c++) { wr[c] = swr[c]; wi[c] = swi[c]; }
    const float4* cr4 = (const float4*)crb;
    const float4* ci4 = (const float4*)cib;
    float4* outr = (float4*)(out + (long long)bf * T);
    float4* outi = (float4*)(out + BFT + (long long)bf * T);
    for (int i = tid; i < T4; i += 128) {
        float4 orv = make_float4(0.f, 0.f, 0.f, 0.f);
        float4 oiv = make_float4(0.f, 0.f, 0.f, 0.f);
        #pragma unroll
        for (int c = 0; c < 8; c++) {
            float4 xr = cr4[c * FT4 + i];
            float4 xi = ci4[c * FT4 + i];
            orv.x = fmaf(wr[c], xr.x, fmaf(-wi[c], xi.x, orv.x));
            orv.y = fmaf(wr[c], xr.y, fmaf(-wi[c], xi.y, orv.y));
            orv.z = fmaf(wr[c], xr.z, fmaf(-wi[c], xi.z, orv.z));
            orv.w = fmaf(wr[c], xr.w, fmaf(-wi[c], xi.w, orv.w));
            oiv.x = fmaf(wr[c], xi.x, fmaf(wi[c], xr.x, oiv.x));
            oiv.y = fmaf(wr[c], xi.y, fmaf(wi[c], xr.y, oiv.y));
            oiv.z = fmaf(wr[c], xi.z, fmaf(wi[c], xr.z, oiv.z));
            oiv.w = fmaf(wr[c], xi.w, fmaf(wi[c], xr.w, oiv.w));
        }
        outr[i] = orv;
        outi[i] = oiv;
    }
}

// ---------------------------------------------------------------------------
extern "C" void kernel_launch(void* const* d_in, const int* in_sizes, int n_in,
                              void* d_out, int out_size) {
    const float* sm = (const float*)d_in[0];
    const float* nm = (const float*)d_in[1];
    const float* cr = (const float*)d_in[2];
    const float* ci = (const float*)d_in[3];
    float* out = (float*)d_out;

    mask_max_part<<<64, 384>>>(sm, nm);
    mask_recip_kernel<<<16, 384>>>();
    mvdr_fused_kernel<<<BF, 128>>>(sm, nm, cr, ci, out);
}

// round 12
// speedup vs baseline: 1.8929x; 1.0856x over previous
#include <cuda_runtime.h>

#define EPS     1e-8f
#define PSD_EPS 1e-5f

constexpr int B = 8, C = 8, F = 257, T = 1500;
constexpr int BF  = B * F;                       // 2056
constexpr long long FT  = (long long)F * T;      // 385500
constexpr long long BFT = (long long)B * F * T;  // 3084000
constexpr int T2 = T / 2;                        // 750
constexpr int T4 = T / 4;                        // 375
constexpr int FT2 = (int)(FT / 2);               // 192750
constexpr int NCH = 16;                          // F-chunks for mask max

// Scratch (no allocations allowed)
__device__ float g_pmax[2][B][NCH][T];
__device__ float g_recip[2][B][T];

// ---------------------------------------------------------------------------
// Kernel 1a: partial max over F-chunk of |mask|, float4 along t.
// grid = 2*B*NCH = 256 blocks, 384 threads (375 active).
// ---------------------------------------------------------------------------
__global__ void mask_max_part(const float* __restrict__ sm,
                              const float* __restrict__ nm) {
    int blk = blockIdx.x;
    int chunk = blk & (NCH - 1), b = (blk >> 4) & 7, m = blk >> 7;
    int i = threadIdx.x;
    if (i >= T4) return;
    // F = 257 = 17 + 15*16
    int fs = chunk ? 17 + (chunk - 1) * 16 : 0;
    int fe = fs + (chunk ? 16 : 17);
    const float4* src = (const float4*)((m ? nm : sm) + (long long)b * FT);
    float4 mx = make_float4(0.f, 0.f, 0.f, 0.f);
    #pragma unroll 4
    for (int f = fs; f < fe; f++) {
        float4 v = src[(long long)f * T4 + i];
        mx.x = fmaxf(mx.x, fabsf(v.x));
        mx.y = fmaxf(mx.y, fabsf(v.y));
        mx.z = fmaxf(mx.z, fabsf(v.z));
        mx.w = fmaxf(mx.w, fabsf(v.w));
    }
    ((float4*)g_pmax[m][b][chunk])[i] = mx;
}

// Kernel 1b: combine NCH partials -> reciprocal. grid = 16 blocks.
__global__ void mask_recip_kernel() {
    int blk = blockIdx.x;
    int b = blk & 7, m = blk >> 3;
    int i = threadIdx.x;
    if (i >= T4) return;
    float4 a = ((float4*)g_pmax[m][b][0])[i];
    #pragma unroll
    for (int c = 1; c < NCH; c++) {
        float4 v = ((float4*)g_pmax[m][b][c])[i];
        a.x = fmaxf(a.x, v.x); a.y = fmaxf(a.y, v.y);
        a.z = fmaxf(a.z, v.z); a.w = fmaxf(a.w, v.w);
    }
    float4 r;
    r.x = 1.0f / (a.x + EPS); r.y = 1.0f / (a.y + EPS);
    r.z = 1.0f / (a.z + EPS); r.w = 1.0f / (a.w + EPS);
    ((float4*)g_recip[m][b])[i] = r;
}

// ---------------------------------------------------------------------------
// Fused kernel: PSD accumulate (staging cm slice to smem) -> reduce ->
// 64-thread-parallel solve -> beamform from smem. One block per (b,f).
// ---------------------------------------------------------------------------
__device__ __forceinline__ int pidx(int c, int d) {
    return c * 7 - (c * (c - 1)) / 2 + (d - c - 1);
}

__device__ __forceinline__ void getS(const float* a, float invs,
                                     int r, int c, float& re, float& im) {
    const float IM0 = PSD_EPS + EPS;
    if (r == c)      { re = a[r] * invs;                 im = IM0; }
    else if (r < c)  { int p = pidx(r, c);
                       re = a[8 + 2 * p] * invs;         im = a[9 + 2 * p] * invs + IM0; }
    else             { int p = pidx(c, r);
                       re = a[8 + 2 * p] * invs;         im = -a[9 + 2 * p] * invs + IM0; }
}

__device__ __forceinline__ void accum_point(float* acc, const float* xr,
                                            const float* xi, float ms, float mn) {
    acc[64]  += ms;
    acc[129] += mn;
    #pragma unroll
    for (int c = 0; c < 8; c++) {
        float p = fmaf(xr[c], xr[c], xi[c] * xi[c]);
        acc[c]      = fmaf(ms, p, acc[c]);
        acc[65 + c] = fmaf(mn, p, acc[65 + c]);
    }
    #pragma unroll
    for (int c = 0; c < 8; c++) {
        #pragma unroll
        for (int d = c + 1; d < 8; d++) {
            int p = pidx(c, d);
            float orr = fmaf(xr[c], xr[d], xi[c] * xi[d]);
            float oii = fmaf(xi[c], xr[d], -xr[c] * xi[d]);
            acc[8 + 2 * p]  = fmaf(ms, orr, acc[8 + 2 * p]);
            acc[9 + 2 * p]  = fmaf(ms, oii, acc[9 + 2 * p]);
            acc[73 + 2 * p] = fmaf(mn, orr, acc[73 + 2 * p]);
            acc[74 + 2 * p] = fmaf(mn, oii, acc[74 + 2 * p]);
        }
    }
}

constexpr int DYN_SMEM = 16 * T * (int)sizeof(float);   // 96000 B: xr[8][T], xi[8][T]

__global__ __launch_bounds__(128) void mvdr_fused_kernel(
    const float* __restrict__ sm, const float* __restrict__ nm,
    const float* __restrict__ cr, const float* __restrict__ ci,
    float* __restrict__ out) {
    extern __shared__ float tile[];          // [0..8T) = re, [8T..16T) = im
    float* xr_s = tile;
    float* xi_s = tile + 8 * T;

    int bf = blockIdx.x;
    int b = bf / F, f = bf % F;
    int tid = threadIdx.x;
    int lane = tid & 31, wid = tid >> 5;

    const float* crb = cr + (long long)b * C * FT + (long long)f * T;
    const float* cib = ci + (long long)b * C * FT + (long long)f * T;
    const float2* cr2 = (const float2*)crb;
    const float2* ci2 = (const float2*)cib;
    const float2* smb = (const float2*)(sm + (long long)b * FT + (long long)f * T);
    const float2* nmb = (const float2*)(nm + (long long)b * FT + (long long)f * T);
    const float2* rs = (const float2*)(g_recip[0][b]);
    const float2* rn = (const float2*)(g_recip[1][b]);

    // ---- Phase A: PSD accumulation (float2 along t) + smem staging ----
    float acc[130];
    #pragma unroll
    for (int k = 0; k < 130; k++) acc[k] = 0.f;

    for (int i = tid; i < T2; i += 128) {
        float2 a = smb[i], ra = rs[i], bm = nmb[i], rb = rn[i];
        float xr0[8], xi0[8], xr1[8], xi1[8];
        #pragma unroll
        for (int c = 0; c < 8; c++) {
            float2 vr = cr2[c * FT2 + i];
            float2 vi = ci2[c * FT2 + i];
            xr0[c] = vr.x; xr1[c] = vr.y;
            xi0[c] = vi.x; xi1[c] = vi.y;
            ((float2*)(xr_s + c * T))[i] = vr;
            ((float2*)(xi_s + c * T))[i] = vi;
        }
        accum_point(acc, xr0, xi0, a.x * ra.x, bm.x * rb.x);
        accum_point(acc, xr1, xi1, a.y * ra.y, bm.y * rb.y);
    }

    // ---- Phase B: deterministic reduction (warp shfl + cross-warp smem) ----
    __shared__ float sh[4][132];
    __shared__ float sacc[130];
    #pragma unroll
    for (int k = 0; k < 130; k++) {
        float v = acc[k];
        v += __shfl_down_sync(0xffffffffu, v, 16);
        v += __shfl_down_sync(0xffffffffu, v, 8);
        v += __shfl_down_sync(0xffffffffu, v, 4);
        v += __shfl_down_sync(0xffffffffu, v, 2);
        v += __shfl_down_sync(0xffffffffu, v, 1);
        if (lane == 0) sh[wid][k] = v;
    }
    __syncthreads();
    for (int k = tid; k < 130; k += 128)
        sacc[k] = sh[0][k] + sh[1][k] + sh[2][k] + sh[3][k];
    __syncthreads();

    // ---- Phase C: entry-parallel solve (threads 0..63) ----
    __shared__ float rowr[8], rowi[8], colr[8], coli[8];
    __shared__ float sur[8], sui[8], strv[2];
    __shared__ float swr[8], swi[8];
    const float* aS = &sacc[0];
    const float* aN = &sacc[65];
    const float IM0 = PSD_EPS + EPS;
    int i8 = tid >> 3, j8 = tid & 7;
    float nr = 0.f, ni = 0.f;

    if (tid < 64) {
        float invd = 1.0f / fmaxf(aN[64], PSD_EPS);
        if (i8 == j8)      { nr = aN[i8] * invd + EPS;  ni = IM0; }
        else if (i8 < j8)  { int p = pidx(i8, j8);
                             nr = aN[8 + 2 * p] * invd; ni = aN[9 + 2 * p] * invd + IM0; }
        else               { int p = pidx(j8, i8);
                             nr = aN[8 + 2 * p] * invd; ni = -aN[9 + 2 * p] * invd + IM0; }
    }

    // Gauss-Jordan, no pivoting (matrix is strongly diagonally dominant)
    #pragma unroll
    for (int k = 0; k < 8; k++) {
        if (tid < 64) {
            if (i8 == k) { rowr[j8] = nr; rowi[j8] = ni; }
            if (j8 == k) { colr[i8] = nr; coli[i8] = ni; }
        }
        __syncthreads();
        if (tid < 64) {
            float pr = rowr[k], pi = rowi[k];
            float s = 1.0f / fmaf(pr, pr, pi * pi);
            float qr = pr * s, qi = -pi * s;
            if (i8 == k) {
                if (j8 == k) { nr = qr; ni = qi; }
                else { float ar = nr, ai = ni;
                       nr = ar * qr - ai * qi; ni = ar * qi + ai * qr; }
            } else {
                float fr = colr[i8], fi = coli[i8];
                float gr = fr * qr - fi * qi, gi = fr * qi + fi * qr;
                if (j8 == k) { nr = -gr; ni = -gi; }
                else {
                    float br = rowr[j8], bi = rowi[j8];
                    nr -= gr * br - gi * bi;
                    ni -= gr * bi + gi * br;
                }
            }
        }
        __syncthreads();
    }

    if (tid < 64) {
        ni += EPS;
        float invs = 1.0f / fmaxf(aS[64], PSD_EPS);
        float sr, si;
        getS(aS, invs, j8, i8, sr, si);
        float tre = nr * sr - ni * si, tim = nr * si + ni * sr;
        getS(aS, invs, j8, 0, sr, si);
        float ue = nr * sr - ni * si, uim = nr * si + ni * sr;
        #pragma unroll
        for (int o = 1; o < 8; o <<= 1) {
            ue  += __shfl_xor_sync(0xffffffffu, ue, o);
            uim += __shfl_xor_sync(0xffffffffu, uim, o);
        }
        if (j8 == 0) { sur[i8] = ue; sui[i8] = uim; }
        #pragma unroll
        for (int o = 16; o >= 1; o >>= 1) {
            tre += __shfl_down_sync(0xffffffffu, tre, o);
            tim += __shfl_down_sync(0xffffffffu, tim, o);
        }
        if (lane == 0) { sh[wid][0] = tre; sh[wid][1] = tim; }
    }
    __syncthreads();
    if (tid == 0) {
        strv[0] = EPS + sh[0][0] + sh[1][0];
        strv[1] = sh[0][1] + sh[1][1];
    }
    __syncthreads();
    if (tid < 8) {
        float trr = strv[0], tri = strv[1];
        float tm = 1.0f / fmaf(trr, trr, tri * tri);
        float ur = sur[tid], ui = sui[tid];
        float wr = (ur * trr + ui * tri) * tm;
        float wi = (ui * trr - ur * tri) * tm;
        swr[tid] = wr;
        swi[tid] = -wi;                           // conj(weight)
    }
    __syncthreads();

    // ---- Phase D: beamform from smem, float4 along t ----
    float wr[8], wi[8];
    #pragma unroll
    for (int c = 0; c < 8; c++) { wr[c] = swr[c]; wi[c] = swi[c]; }
    float4* outr = (float4*)(out + (long long)bf * T);
    float4* outi = (float4*)(out + BFT + (long long)bf * T);
    for (int i = tid; i < T4; i += 128) {
        float4 orv = make_float4(0.f, 0.f, 0.f, 0.f);
        float4 oiv = make_float4(0.f, 0.f, 0.f, 0.f);
        #pragma unroll
        for (int c = 0; c < 8; c++) {
            float4 xr = ((const float4*)(xr_s + c * T))[i];
            float4 xi = ((const float4*)(xi_s + c * T))[i];
            orv.x = fmaf(wr[c], xr.x, fmaf(-wi[c], xi.x, orv.x));
            orv.y = fmaf(wr[c], xr.y, fmaf(-wi[c], xi.y, orv.y));
            orv.z = fmaf(wr[c], xr.z, fmaf(-wi[c], xi.z, orv.z));
            orv.w = fmaf(wr[c], xr.w, fmaf(-wi[c], xi.w, orv.w));
            oiv.x = fmaf(wr[c], xi.x, fmaf(wi[c], xr.x, oiv.x));
            oiv.y = fmaf(wr[c], xi.y, fmaf(wi[c], xr.y, oiv.y));
            oiv.z = fmaf(wr[c], xi.z, fmaf(wi[c], xr.z, oiv.z));
            oiv.w = fmaf(wr[c], xi.w, fmaf(wi[c], xr.w, oiv.w));
        }
        outr[i] = orv;
        outi[i] = oiv;
    }
}

// ---------------------------------------------------------------------------
extern "C" void kernel_launch(void* const* d_in, const int* in_sizes, int n_in,
                              void* d_out, int out_size) {
    const float* sm = (const float*)d_in[0];
    const float* nm = (const float*)d_in[1];
    const float* cr = (const float*)d_in[2];
    const float* ci = (const float*)d_in[3];
    float* out = (float*)d_out;

    // Immediate host-side attribute set (not a stream op; capture-legal,
    // idempotent, no allocation).
    cudaFuncSetAttribute(mvdr_fused_kernel,
                         cudaFuncAttributeMaxDynamicSharedMemorySize, DYN_SMEM);

    mask_max_part<<<2 * B * NCH, 384>>>(sm, nm);
    mask_recip_kernel<<<16, 384>>>();
    mvdr_fused_kernel<<<BF, 128, DYN_SMEM>>>(sm, nm, cr, ci, out);
}